// round 1
// baseline (speedup 1.0000x reference)
#include <cuda_runtime.h>
#include <math.h>

#define NPTS_MAX 1000000
#define DIM 64
#define PPATCH 4096
#define TPAD 68   // padded row stride (floats) for SMEM tiles: conflict-free lane rows, float4-aligned

// ---------------- device scratch (no cudaMalloc allowed) ----------------
__device__ unsigned long long g_csum[PPATCH * 3];
__device__ unsigned int       g_cnt[PPATCH];
__device__ float4             g_centers[PPATCH];
__device__ float              g_AB[DIM * 128];   // row k: [0..63]=A[k][:], [64..127]=B[k][:]
__device__ float              g_cvec[DIM];

// ---------------- packed fp32x2 helpers (Blackwell dual-rate FMA) ----------------
__device__ __forceinline__ unsigned long long pack2(float x) {
    unsigned long long r;
    asm("mov.b64 %0, {%1, %1};" : "=l"(r) : "f"(x));
    return r;
}
__device__ __forceinline__ void unpack2(unsigned long long v, float &lo, float &hi) {
    asm("mov.b64 {%0, %1}, %2;" : "=f"(lo), "=f"(hi) : "l"(v));
}
__device__ __forceinline__ unsigned long long fma2(unsigned long long a, unsigned long long b,
                                                   unsigned long long c) {
    unsigned long long d;
    asm("fma.rn.f32x2 %0, %1, %2, %3;" : "=l"(d) : "l"(a), "l"(b), "l"(c));
    return d;
}

// ---------------- kernel 1: zero accumulators (graph-replay safe) ----------------
__global__ void k_zero() {
    int i = blockIdx.x * blockDim.x + threadIdx.x;
    if (i < PPATCH * 3) g_csum[i] = 0ull;
    if (i < PPATCH)     g_cnt[i] = 0u;
}

// ---------------- kernel 2: deterministic fixed-point segment sum ----------------
__global__ void k_scatter(const float* __restrict__ coord, const int* __restrict__ ids, int n) {
    int i = blockIdx.x * blockDim.x + threadIdx.x;
    if (i >= n) return;
    int p = ids[i];
    float c0 = coord[3 * i + 0];
    float c1 = coord[3 * i + 1];
    float c2 = coord[3 * i + 2];
    const float S = 4294967296.0f;  // coord in [0,1): fits u64 with huge headroom
    atomicAdd(&g_csum[p * 3 + 0], (unsigned long long)(c0 * S));
    atomicAdd(&g_csum[p * 3 + 1], (unsigned long long)(c1 * S));
    atomicAdd(&g_csum[p * 3 + 2], (unsigned long long)(c2 * S));
    atomicAdd(&g_cnt[p], 1u);
}

// ---------------- kernel 3: centers = sum / max(cnt,1) ----------------
__global__ void k_centers() {
    int p = blockIdx.x * blockDim.x + threadIdx.x;
    if (p >= PPATCH) return;
    const double inv = 1.0 / 4294967296.0;
    double cnt = (double)max(g_cnt[p], 1u);
    float cx = (float)((double)g_csum[p * 3 + 0] * inv / cnt);
    float cy = (float)((double)g_csum[p * 3 + 1] * inv / cnt);
    float cz = (float)((double)g_csum[p * 3 + 2] * inv / cnt);
    g_centers[p] = make_float4(cx, cy, cz, 0.0f);
}

// ---------------- kernel 4: fold dw/pw into A, B, c ----------------
// A[k][j] = dw_w[k]*pw_W[k][j]
// B[k][j] = sum_u W2[k][u]*dw_w[u]*pw_W[u][j]
// c[j]    = sum_u (b2[u]*dw_w[u]+dw_b[u])*pw_W[u][j] + pw_b[j]
__global__ void k_prep(const float* __restrict__ W2, const float* __restrict__ dw_w,
                       const float* __restrict__ dw_b, const float* __restrict__ pw_W,
                       const float* __restrict__ pw_b, const float* __restrict__ b2) {
    int t = blockIdx.x * blockDim.x + threadIdx.x;
    if (t >= DIM * DIM) return;
    int k = t >> 6;
    int j = t & 63;
    g_AB[k * 128 + j] = dw_w[k] * pw_W[k * 64 + j];
    float s = 0.0f;
    for (int u = 0; u < 64; ++u)
        s += W2[k * 64 + u] * (dw_w[u] * pw_W[u * 64 + j]);
    g_AB[k * 128 + 64 + j] = s;
    if (k == 0) {
        float cv = pw_b[j];
        for (int u = 0; u < 64; ++u)
            cv += (b2[u] * dw_w[u] + dw_b[u]) * pw_W[u * 64 + j];
        g_cvec[j] = cv;
    }
}

// one K-step of the fused dual GEMM: acc[j-pair] += x_k*(A row pair) + g_k*(B row pair)
__device__ __forceinline__ void kstep(float xc, float gc, const ulonglong2* __restrict__ Ar,
                                      unsigned long long* acc) {
    unsigned long long xp = pack2(xc);
    unsigned long long gp = pack2(gc);
    const ulonglong2* Br = Ar + 16;
#pragma unroll
    for (int q = 0; q < 16; ++q) {
        ulonglong2 av = Ar[q];
        ulonglong2 bv = Br[q];
        acc[2 * q]     = fma2(xp, av.x, acc[2 * q]);
        acc[2 * q + 1] = fma2(xp, av.y, acc[2 * q + 1]);
        acc[2 * q]     = fma2(gp, bv.x, acc[2 * q]);
        acc[2 * q + 1] = fma2(gp, bv.y, acc[2 * q + 1]);
    }
}

// ---------------- kernel 5: fused main pass ----------------
// SMEM layout (floats):
//   [0, 8192)        ABs (A|B interleaved rows)
//   [8192, 8384)     W1s (3x64)
//   [8384, 8448)     b1s
//   [8448, 8512)     lngs
//   [8512, 8576)     lnbs
//   [8576, 8640)     cs
//   [8704, 26112)    per-warp tiles: 4 warps x (xs[32][TPAD] + gs[32][TPAD])
#define SMEM_FLOATS 26112

__global__ void __launch_bounds__(128)
k_main(const float* __restrict__ x, const float* __restrict__ coord,
       const int* __restrict__ ids, const float* __restrict__ W1,
       const float* __restrict__ b1, const float* __restrict__ ln_g,
       const float* __restrict__ ln_b, float* __restrict__ out, int n, int ntiles) {
    extern __shared__ float sm[];
    float* ABs  = sm;
    float* W1s  = sm + 8192;
    float* b1s  = sm + 8384;
    float* lngs = sm + 8448;
    float* lnbs = sm + 8512;
    float* cs   = sm + 8576;
    float* tiles = sm + 8704;

    int tid = threadIdx.x;
    int lane = tid & 31;
    int warp = tid >> 5;

    for (int i = tid; i < 8192; i += blockDim.x) ABs[i] = g_AB[i];
    for (int i = tid; i < 192; i += blockDim.x) W1s[i] = W1[i];
    for (int i = tid; i < 64; i += blockDim.x) {
        b1s[i]  = b1[i];
        lngs[i] = ln_g[i];
        lnbs[i] = ln_b[i];
        cs[i]   = g_cvec[i];
    }
    __syncthreads();

    float* xs = tiles + warp * (2 * 32 * TPAD);
    float* gs = xs + 32 * TPAD;
    const ulonglong2* ab2 = (const ulonglong2*)ABs;

    int gwarp  = blockIdx.x * (blockDim.x >> 5) + warp;
    int nwarps = gridDim.x * (blockDim.x >> 5);

    for (int tile = gwarp; tile < ntiles; tile += nwarps) {
        int base = tile * 32;

        // --- cooperative coalesced load of x tile (32 points x 64 ch) ---
#pragma unroll
        for (int i = 0; i < 16; ++i) {
            int idx = i * 128 + lane * 4;
            int p = idx >> 6, k = idx & 63;
            float4 v = make_float4(0.f, 0.f, 0.f, 0.f);
            if (base + p < n) v = *(const float4*)&x[(size_t)(base + p) * 64 + k];
            *(float4*)&xs[p * TPAD + k] = v;
        }

        // --- per-thread point: delta + MLP front (3->64 + exact-erf GELU) ---
        int pt = base + lane;
        float d0 = 0.f, d1 = 0.f, d2 = 0.f;
        if (pt < n) {
            int pid = ids[pt];
            float4 cc = g_centers[pid];
            d0 = coord[3 * pt + 0] - cc.x;
            d1 = coord[3 * pt + 1] - cc.y;
            d2 = coord[3 * pt + 2] - cc.z;
        }
#pragma unroll 4
        for (int j = 0; j < 64; j += 4) {
            float gg[4];
#pragma unroll
            for (int q = 0; q < 4; ++q) {
                int jj = j + q;
                float h = fmaf(d2, W1s[128 + jj],
                          fmaf(d1, W1s[64 + jj],
                          fmaf(d0, W1s[jj], b1s[jj])));
                gg[q] = h * normcdff(h);  // exact erf GELU: x * Phi(x)
            }
            *(float4*)&gs[lane * TPAD + j] = make_float4(gg[0], gg[1], gg[2], gg[3]);
        }
        __syncwarp();  // xs rows written cooperatively, read per-lane below

        // --- fused dual GEMM: out2 = x@A + g@B + c (packed f32x2) ---
        unsigned long long acc[32];
#pragma unroll
        for (int q = 0; q < 32; ++q)
            acc[q] = *(const unsigned long long*)&cs[2 * q];

        const float* xrow = &xs[lane * TPAD];
        const float* grow = &gs[lane * TPAD];
#pragma unroll 1
        for (int k0 = 0; k0 < 64; k0 += 4) {
            float4 xv = *(const float4*)&xrow[k0];
            float4 gv = *(const float4*)&grow[k0];
            kstep(xv.x, gv.x, ab2 + (k0 + 0) * 32, acc);
            kstep(xv.y, gv.y, ab2 + (k0 + 1) * 32, acc);
            kstep(xv.z, gv.z, ab2 + (k0 + 2) * 32, acc);
            kstep(xv.w, gv.w, ab2 + (k0 + 3) * 32, acc);
        }

        // --- LayerNorm epilogue in registers ---
        float vsum = 0.f, vsq = 0.f;
#pragma unroll
        for (int q = 0; q < 32; ++q) {
            float lo, hi;
            unpack2(acc[q], lo, hi);
            vsum += lo + hi;
            vsq  += lo * lo + hi * hi;
        }
        float mu   = vsum * 0.015625f;
        float var  = vsq * 0.015625f - mu * mu;
        float rstd = rsqrtf(var + 1e-5f);

        float* orow = &xs[lane * TPAD];  // reuse x tile for output transpose
#pragma unroll
        for (int q = 0; q < 32; ++q) {
            float lo, hi;
            unpack2(acc[q], lo, hi);
            float o0 = (lo - mu) * rstd * lngs[2 * q]     + lnbs[2 * q];
            float o1 = (hi - mu) * rstd * lngs[2 * q + 1] + lnbs[2 * q + 1];
            *(float2*)&orow[2 * q] = make_float2(o0, o1);
        }
        __syncwarp();

        // --- cooperative coalesced store ---
#pragma unroll
        for (int i = 0; i < 16; ++i) {
            int idx = i * 128 + lane * 4;
            int p = idx >> 6, k = idx & 63;
            int gpt = base + p;
            if (gpt < n)
                *(float4*)&out[(size_t)gpt * 64 + k] = *(const float4*)&xs[p * TPAD + k];
        }
        __syncwarp();  // xs reused for next tile's load
    }
}

// ---------------- launch ----------------
extern "C" void kernel_launch(void* const* d_in, const int* in_sizes, int n_in,
                              void* d_out, int out_size) {
    const float* x     = (const float*)d_in[0];
    const float* coord = (const float*)d_in[1];
    const int*   ids   = (const int*)d_in[2];
    const float* W1    = (const float*)d_in[3];
    const float* b1    = (const float*)d_in[4];
    const float* W2    = (const float*)d_in[5];
    const float* b2    = (const float*)d_in[6];
    const float* dw_w  = (const float*)d_in[7];
    const float* dw_b  = (const float*)d_in[8];
    const float* pw_W  = (const float*)d_in[9];
    const float* pw_b  = (const float*)d_in[10];
    const float* ln_g  = (const float*)d_in[11];
    const float* ln_b  = (const float*)d_in[12];
    float* out = (float*)d_out;

    int n = in_sizes[0] / DIM;  // N from x element count

    k_zero<<<(PPATCH * 3 + 255) / 256, 256>>>();
    k_scatter<<<(n + 255) / 256, 256>>>(coord, ids, n);
    k_centers<<<(PPATCH + 255) / 256, 256>>>();
    k_prep<<<(DIM * DIM + 255) / 256, 256>>>(W2, dw_w, dw_b, pw_W, pw_b, b2);

    int ntiles = (n + 31) / 32;
    size_t smem = SMEM_FLOATS * sizeof(float);  // 104448 B -> 2 CTAs/SM
    cudaFuncSetAttribute(k_main, cudaFuncAttributeMaxDynamicSharedMemorySize, (int)smem);
    k_main<<<304, 128, smem>>>(x, coord, ids, W1, b1, ln_g, ln_b, out, n, ntiles);
}

// round 3
// speedup vs baseline: 1.9183x; 1.9183x over previous
#include <cuda_runtime.h>
#include <cuda_bf16.h>
#include <math.h>
#include <stdint.h>

#define DIM 64
#define PPATCH 4096
#define TILE 128
#define NT 128

// ---------------- device scratch ----------------
__device__ unsigned long long g_s01[PPATCH];   // (sum c0)<<32 | (sum c1), fixed-point 2^22
__device__ unsigned long long g_s2c[PPATCH];   // (sum c2)<<32 | count
__device__ float4             g_centers[PPATCH];
__device__ float              g_AB[DIM * 128]; // row k: [0..63]=A[k][:], [64..127]=B[k][:]
__device__ float              g_cvec[DIM];

// ---------------- helpers ----------------
__device__ __forceinline__ uint32_t smem_u32(const void* p) {
    uint32_t a;
    asm("{ .reg .u64 t; cvta.to.shared.u64 t, %1; cvt.u32.u64 %0, t; }" : "=r"(a) : "l"(p));
    return a;
}
__device__ __forceinline__ uint32_t swz(uint32_t x) { return x ^ ((x >> 3) & 0x70); }

__device__ __forceinline__ void ldsm4(uint32_t &r0, uint32_t &r1, uint32_t &r2, uint32_t &r3,
                                      uint32_t addr) {
    asm volatile("ldmatrix.sync.aligned.m8n8.x4.shared.b16 {%0,%1,%2,%3}, [%4];"
                 : "=r"(r0), "=r"(r1), "=r"(r2), "=r"(r3) : "r"(addr));
}
__device__ __forceinline__ void ldsm4t(uint32_t &r0, uint32_t &r1, uint32_t &r2, uint32_t &r3,
                                       uint32_t addr) {
    asm volatile("ldmatrix.sync.aligned.m8n8.x4.trans.shared.b16 {%0,%1,%2,%3}, [%4];"
                 : "=r"(r0), "=r"(r1), "=r"(r2), "=r"(r3) : "r"(addr));
}
__device__ __forceinline__ void mma16816(float (&d)[4], uint32_t a0, uint32_t a1, uint32_t a2,
                                         uint32_t a3, uint32_t b0, uint32_t b1) {
    asm volatile(
        "mma.sync.aligned.m16n8k16.row.col.f32.bf16.bf16.f32 "
        "{%0,%1,%2,%3}, {%4,%5,%6,%7}, {%8,%9}, {%0,%1,%2,%3};"
        : "+f"(d[0]), "+f"(d[1]), "+f"(d[2]), "+f"(d[3])
        : "r"(a0), "r"(a1), "r"(a2), "r"(a3), "r"(b0), "r"(b1));
}

__device__ __forceinline__ uint64_t pack4bf(float a, float b, float c, float d) {
    __nv_bfloat162 p0 = __floats2bfloat162_rn(a, b);
    __nv_bfloat162 p1 = __floats2bfloat162_rn(c, d);
    uint32_t u0 = *reinterpret_cast<uint32_t*>(&p0);
    uint32_t u1 = *reinterpret_cast<uint32_t*>(&p1);
    return (uint64_t)u0 | ((uint64_t)u1 << 32);
}
__device__ __forceinline__ float bfhi(float v) {
    return __bfloat162float(__float2bfloat16_rn(v));
}

// exact-erf GELU via Abramowitz-Stegun 26.2.17 normal CDF (|err| < 7.5e-8)
__device__ __forceinline__ float gelu_erf(float h) {
    float u = fabsf(h);
    float t = __frcp_rn(fmaf(0.2316419f, u, 1.0f));
    float phi = 0.3989422804f * __expf(-0.5f * u * u);
    float poly = t * fmaf(t, fmaf(t, fmaf(t, fmaf(t, 1.330274429f, -1.821255978f),
                                          1.781477937f), -0.356563782f), 0.319381530f);
    float tail = phi * poly;          // 1 - Phi(u)
    float cdf = (h >= 0.f) ? (1.0f - tail) : tail;
    return h * cdf;
}

// ---------------- kernel 1: scatter (fixed-point, 2 atomics/pt) + weight fold ----------------
__global__ void k_front(const float* __restrict__ coord, const int* __restrict__ ids, int n,
                        int nb_scatter, const float* __restrict__ W2,
                        const float* __restrict__ dw_w, const float* __restrict__ dw_b,
                        const float* __restrict__ pw_W, const float* __restrict__ pw_b,
                        const float* __restrict__ b2) {
    int b = blockIdx.x;
    if (b < nb_scatter) {
        int i = b * 256 + threadIdx.x;
        if (i < n) {
            int p = ids[i];
            const float S = 4194304.0f;  // 2^22
            unsigned long long u0 = (unsigned long long)(coord[3 * i + 0] * S + 0.5f);
            unsigned long long u1 = (unsigned long long)(coord[3 * i + 1] * S + 0.5f);
            unsigned long long u2 = (unsigned long long)(coord[3 * i + 2] * S + 0.5f);
            atomicAdd(&g_s01[p], (u0 << 32) | u1);
            atomicAdd(&g_s2c[p], (u2 << 32) | 1ull);
        }
    } else {
        int t = (b - nb_scatter) * 256 + threadIdx.x;
        if (t >= DIM * DIM) return;
        int k = t >> 6, j = t & 63;
        g_AB[k * 128 + j] = dw_w[k] * pw_W[k * 64 + j];
        float s = 0.0f;
        for (int u = 0; u < 64; ++u)
            s += W2[k * 64 + u] * (dw_w[u] * pw_W[u * 64 + j]);
        g_AB[k * 128 + 64 + j] = s;
        if (k == 0) {
            float cv = pw_b[j];
            for (int u = 0; u < 64; ++u)
                cv += (b2[u] * dw_w[u] + dw_b[u]) * pw_W[u * 64 + j];
            g_cvec[j] = cv;
        }
    }
}

// ---------------- kernel 2: centers + re-zero (replay-safe) ----------------
__global__ void k_centers() {
    int p = blockIdx.x * 256 + threadIdx.x;
    if (p >= PPATCH) return;
    unsigned long long a = g_s01[p], b = g_s2c[p];
    unsigned int cnt = (unsigned int)(b & 0xffffffffull);
    double d = (1.0 / 4194304.0) / (double)max(cnt, 1u);
    g_centers[p] = make_float4((float)((double)(a >> 32) * d),
                               (float)((double)(a & 0xffffffffull) * d),
                               (float)((double)(b >> 32) * d), 0.0f);
    g_s01[p] = 0ull;
    g_s2c[p] = 0ull;
}

// ---------------- kernel 3: main fused pass (mma.sync bf16) ----------------
// SMEM byte layout (per CTA):
//   XHI 0 (16KB) XLO 16384 GHI 32768 GLO 49152            operand tiles, 128 rows x 128B SW128
//   WAH 65536 WAL 73728 WBH 81920 WBL 90112  (8KB each)   weights k-major, 64 rows x 128B
//   cvs 98304(256B) W1s 98560(768B) b1s 99328 lng 99584 lnb 99840
//   staging (fp32, stride 68) overlaps [0, 34816)
#define XHI   0u
#define XLO   16384u
#define GHI   32768u
#define GLO   49152u
#define WAH   65536u
#define WAL   73728u
#define WBH   81920u
#define WBL   90112u
#define OCV   98304u
#define OW1   98560u
#define OB1   99328u
#define OLNG  99584u
#define OLNB  99840u
#define SMEM_BYTES 100352u

__global__ void __launch_bounds__(NT, 2)
k_main(const float* __restrict__ x, const float* __restrict__ coord,
       const int* __restrict__ ids, const float* __restrict__ W1,
       const float* __restrict__ b1, const float* __restrict__ ln_g,
       const float* __restrict__ ln_b, float* __restrict__ out, int n, int ntiles) {
    extern __shared__ char smx[];
    const uint32_t sb = smem_u32(smx);
    int tid = threadIdx.x;
    int lane = tid & 31;
    int warp = tid >> 5;

    float* cvs = (float*)(smx + OCV);
    float* W1s = (float*)(smx + OW1);
    float* b1s = (float*)(smx + OB1);
    float* lng = (float*)(smx + OLNG);
    float* lnb = (float*)(smx + OLNB);
    for (int i = tid; i < 192; i += NT) W1s[i] = W1[i];
    for (int i = tid; i < 64; i += NT) {
        b1s[i] = b1[i];
        lng[i] = ln_g[i];
        lnb[i] = ln_b[i];
        cvs[i] = g_cvec[i];
    }
    // weights -> bf16 hi/lo, k-major rows (row k, 64 n cols, 128B), swizzled
    for (int i = tid; i < DIM * DIM; i += NT) {
        int k = i >> 6, j = i & 63;
        float fa = g_AB[k * 128 + j];
        float fb = g_AB[k * 128 + 64 + j];
        float fah = bfhi(fa), fbh = bfhi(fb);
        uint32_t off = swz((uint32_t)(k * 128 + j * 2));
        *(__nv_bfloat16*)(smx + WAH + off) = __float2bfloat16_rn(fah);
        *(__nv_bfloat16*)(smx + WAL + off) = __float2bfloat16_rn(fa - fah);
        *(__nv_bfloat16*)(smx + WBH + off) = __float2bfloat16_rn(fbh);
        *(__nv_bfloat16*)(smx + WBL + off) = __float2bfloat16_rn(fb - fbh);
    }
    __syncthreads();

    const int m0 = warp * 32;
    const int lm = (lane & 7) + (lane & 8);   // row-within-16 for ldmatrix quadrants
    const int lc = (lane >> 4) << 3;          // +8 column for upper lanes
    const int q2 = (lane & 3) * 2;
    const int rg = lane >> 2;

    for (int tile = blockIdx.x; tile < ntiles; tile += gridDim.x) {
        int base = tile * TILE;

        // --- load x tile coalesced, split hi/lo, STS swizzled ---
#pragma unroll
        for (int i = 0; i < 16; ++i) {
            int idx = i * 512 + tid * 4;
            int p = idx >> 6, k = idx & 63;
            float4 v = make_float4(0.f, 0.f, 0.f, 0.f);
            if (base + p < n) v = *(const float4*)&x[(size_t)(base + p) * 64 + k];
            float hx = bfhi(v.x), hy = bfhi(v.y), hz = bfhi(v.z), hw = bfhi(v.w);
            uint32_t off = swz((uint32_t)(p * 128 + k * 2));
            *(uint64_t*)(smx + XHI + off) = pack4bf(hx, hy, hz, hw);
            *(uint64_t*)(smx + XLO + off) = pack4bf(v.x - hx, v.y - hy, v.z - hz, v.w - hw);
        }

        // --- front MLP: point = tid; g = gelu(delta@W1+b1); split hi/lo ---
        {
            int pt = base + tid;
            float d0 = 0.f, d1 = 0.f, d2 = 0.f;
            if (pt < n) {
                float4 cc = g_centers[__ldg(&ids[pt])];
                d0 = __ldg(&coord[3 * pt + 0]) - cc.x;
                d1 = __ldg(&coord[3 * pt + 1]) - cc.y;
                d2 = __ldg(&coord[3 * pt + 2]) - cc.z;
            }
#pragma unroll 4
            for (int j = 0; j < 64; j += 4) {
                float gh[4], gl[4];
#pragma unroll
                for (int q = 0; q < 4; ++q) {
                    int jj = j + q;
                    float h = fmaf(d2, W1s[128 + jj],
                              fmaf(d1, W1s[64 + jj],
                              fmaf(d0, W1s[jj], b1s[jj])));
                    float g = gelu_erf(h);
                    gh[q] = bfhi(g);
                    gl[q] = g - gh[q];
                }
                uint32_t off = swz((uint32_t)(tid * 128 + j * 2));
                *(uint64_t*)(smx + GHI + off) = pack4bf(gh[0], gh[1], gh[2], gh[3]);
                *(uint64_t*)(smx + GLO + off) = pack4bf(gl[0], gl[1], gl[2], gl[3]);
            }
        }
        __syncthreads();

        // --- accumulators init with bias c ---
        float acc[2][8][4];
#pragma unroll
        for (int nt = 0; nt < 8; ++nt) {
            float2 cv = *(float2*)&cvs[nt * 8 + q2];
#pragma unroll
            for (int mt = 0; mt < 2; ++mt) {
                acc[mt][nt][0] = cv.x;
                acc[mt][nt][1] = cv.y;
                acc[mt][nt][2] = cv.x;
                acc[mt][nt][3] = cv.y;
            }
        }

        // --- 6 split-precision products on HMMA ---
        const uint32_t abase[6] = {sb + XHI, sb + XHI, sb + XLO, sb + GHI, sb + GHI, sb + GLO};
        const uint32_t wbase[6] = {sb + WAH, sb + WAL, sb + WAH, sb + WBH, sb + WBL, sb + WBH};
#pragma unroll
        for (int p = 0; p < 6; ++p) {
            uint32_t ab = abase[p], wb = wbase[p];
#pragma unroll
            for (int kt = 0; kt < 4; ++kt) {
                uint32_t arow = (uint32_t)((m0 + lm) * 128 + (kt * 16 + lc) * 2);
                uint32_t a0, a1, a2, a3, c0, c1, c2, c3;
                ldsm4(a0, a1, a2, a3, ab + swz(arow));
                ldsm4(c0, c1, c2, c3, ab + swz(arow + 16 * 128));
                uint32_t brow = (uint32_t)((kt * 16 + lm) * 128 + lc * 2);
#pragma unroll
                for (int np = 0; np < 4; ++np) {
                    uint32_t b0, b1r, b2, b3;
                    ldsm4t(b0, b1r, b2, b3, wb + swz(brow + np * 32));
                    mma16816(acc[0][2 * np],     a0, a1, a2, a3, b0, b1r);
                    mma16816(acc[0][2 * np + 1], a0, a1, a2, a3, b2, b3);
                    mma16816(acc[1][2 * np],     c0, c1, c2, c3, b0, b1r);
                    mma16816(acc[1][2 * np + 1], c0, c1, c2, c3, b2, b3);
                }
            }
        }
        __syncthreads();  // all smem reads done before staging overwrites

        // --- LayerNorm epilogue: rows live in lane quads ---
        float* stg = (float*)smx;  // stride 68 floats, overlaps XHI/XLO/GHI
#pragma unroll
        for (int mt = 0; mt < 2; ++mt) {
            float s0 = 0.f, s1 = 0.f, ss0 = 0.f, ss1 = 0.f;
#pragma unroll
            for (int nt = 0; nt < 8; ++nt) {
                float* a = acc[mt][nt];
                s0 += a[0] + a[1];
                ss0 += a[0] * a[0] + a[1] * a[1];
                s1 += a[2] + a[3];
                ss1 += a[2] * a[2] + a[3] * a[3];
            }
            s0 += __shfl_xor_sync(0xffffffffu, s0, 1);
            s0 += __shfl_xor_sync(0xffffffffu, s0, 2);
            ss0 += __shfl_xor_sync(0xffffffffu, ss0, 1);
            ss0 += __shfl_xor_sync(0xffffffffu, ss0, 2);
            s1 += __shfl_xor_sync(0xffffffffu, s1, 1);
            s1 += __shfl_xor_sync(0xffffffffu, s1, 2);
            ss1 += __shfl_xor_sync(0xffffffffu, ss1, 1);
            ss1 += __shfl_xor_sync(0xffffffffu, ss1, 2);
            float mu0 = s0 * 0.015625f, mu1 = s1 * 0.015625f;
            float r0v = rsqrtf(ss0 * 0.015625f - mu0 * mu0 + 1e-5f);
            float r1v = rsqrtf(ss1 * 0.015625f - mu1 * mu1 + 1e-5f);
            int r0 = m0 + mt * 16 + rg;
            int r1 = r0 + 8;
#pragma unroll
            for (int nt = 0; nt < 8; ++nt) {
                int nn = nt * 8 + q2;
                float2 gg = *(float2*)&lng[nn];
                float2 bb = *(float2*)&lnb[nn];
                float* a = acc[mt][nt];
                float2 o0 = make_float2((a[0] - mu0) * r0v * gg.x + bb.x,
                                        (a[1] - mu0) * r0v * gg.y + bb.y);
                float2 o1 = make_float2((a[2] - mu1) * r1v * gg.x + bb.x,
                                        (a[3] - mu1) * r1v * gg.y + bb.y);
                *(float2*)&stg[r0 * 68 + nn] = o0;
                *(float2*)&stg[r1 * 68 + nn] = o1;
            }
        }
        __syncthreads();

        // --- coalesced store ---
#pragma unroll
        for (int i = 0; i < 16; ++i) {
            int idx = i * 512 + tid * 4;
            int p = idx >> 6, k = idx & 63;
            if (base + p < n)
                *(float4*)&out[(size_t)(base + p) * 64 + k] = *(const float4*)&stg[p * 68 + k];
        }
        __syncthreads();  // staging reused as operand buffer next tile
    }
}

// ---------------- launch ----------------
extern "C" void kernel_launch(void* const* d_in, const int* in_sizes, int n_in,
                              void* d_out, int out_size) {
    const float* x     = (const float*)d_in[0];
    const float* coord = (const float*)d_in[1];
    const int*   ids   = (const int*)d_in[2];
    const float* W1    = (const float*)d_in[3];
    const float* b1    = (const float*)d_in[4];
    const float* W2    = (const float*)d_in[5];
    const float* b2    = (const float*)d_in[6];
    const float* dw_w  = (const float*)d_in[7];
    const float* dw_b  = (const float*)d_in[8];
    const float* pw_W  = (const float*)d_in[9];
    const float* pw_b  = (const float*)d_in[10];
    const float* ln_g  = (const float*)d_in[11];
    const float* ln_b  = (const float*)d_in[12];
    float* out = (float*)d_out;

    int n = in_sizes[0] / DIM;
    int nbs = (n + 255) / 256;

    k_front<<<nbs + 16, 256>>>(coord, ids, n, nbs, W2, dw_w, dw_b, pw_W, pw_b, b2);
    k_centers<<<16, 256>>>();

    int ntiles = (n + TILE - 1) / TILE;
    cudaFuncSetAttribute(k_main, cudaFuncAttributeMaxDynamicSharedMemorySize, SMEM_BYTES);
    k_main<<<296, NT, SMEM_BYTES>>>(x, coord, ids, W1, b1, ln_g, ln_b, out, n, ntiles);
}

// round 4
// speedup vs baseline: 2.9376x; 1.5313x over previous
#include <cuda_runtime.h>
#include <cuda_bf16.h>
#include <math.h>
#include <stdint.h>

#define DIM 64
#define PPATCH 4096
#define TILE 256
#define NT 256

// ---------------- device scratch ----------------
__device__ unsigned long long g_s01[PPATCH];
__device__ unsigned long long g_s2c[PPATCH];
__device__ float4             g_centers[PPATCH];
__device__ float              g_AB[DIM * 128]; // row k: [0..63]=A[k][:], [64..127]=B[k][:]
__device__ float              g_cvec[DIM];

// ---------------- helpers ----------------
__device__ __forceinline__ uint32_t smem_u32(const void* p) {
    uint32_t a;
    asm("{ .reg .u64 t; cvta.to.shared.u64 t, %1; cvt.u32.u64 %0, t; }" : "=r"(a) : "l"(p));
    return a;
}
__device__ __forceinline__ uint32_t swz(uint32_t x) { return x ^ ((x >> 3) & 0x70); }

__device__ __forceinline__ void ldsm4(uint32_t &r0, uint32_t &r1, uint32_t &r2, uint32_t &r3,
                                      uint32_t addr) {
    asm volatile("ldmatrix.sync.aligned.m8n8.x4.shared.b16 {%0,%1,%2,%3}, [%4];"
                 : "=r"(r0), "=r"(r1), "=r"(r2), "=r"(r3) : "r"(addr));
}
__device__ __forceinline__ void ldsm4t(uint32_t &r0, uint32_t &r1, uint32_t &r2, uint32_t &r3,
                                       uint32_t addr) {
    asm volatile("ldmatrix.sync.aligned.m8n8.x4.trans.shared.b16 {%0,%1,%2,%3}, [%4];"
                 : "=r"(r0), "=r"(r1), "=r"(r2), "=r"(r3) : "r"(addr));
}
__device__ __forceinline__ void mma16816(float (&d)[4], uint32_t a0, uint32_t a1, uint32_t a2,
                                         uint32_t a3, uint32_t b0, uint32_t b1) {
    asm volatile(
        "mma.sync.aligned.m16n8k16.row.col.f32.bf16.bf16.f32 "
        "{%0,%1,%2,%3}, {%4,%5,%6,%7}, {%8,%9}, {%0,%1,%2,%3};"
        : "+f"(d[0]), "+f"(d[1]), "+f"(d[2]), "+f"(d[3])
        : "r"(a0), "r"(a1), "r"(a2), "r"(a3), "r"(b0), "r"(b1));
}

__device__ __forceinline__ uint32_t pack2bf(float a, float b) {
    __nv_bfloat162 p = __floats2bfloat162_rn(a, b);
    return *reinterpret_cast<uint32_t*>(&p);
}
__device__ __forceinline__ uint64_t pack4bf(float a, float b, float c, float d) {
    return (uint64_t)pack2bf(a, b) | ((uint64_t)pack2bf(c, d) << 32);
}
__device__ __forceinline__ float bfhi(float v) {
    return __bfloat162float(__float2bfloat16_rn(v));
}
// fast tanh-form GELU: h * sigmoid(2 * 0.7978845608 * (h + 0.044715 h^3))
__device__ __forceinline__ float gelu_fast(float h) {
    float p = h * h;
    float c = fmaf(0.0356774081f, p, 0.7978845608f);   // 0.79788456*(1 + 0.044715 h^2)/... folded
    float t = __expf(2.0f * h * c);
    float r = __frcp_rn(t + 1.0f);
    return fmaf(-h, r, h);                              // h * sigmoid(2hc)
}

// ---------------- kernel 1: scatter + weight fold ----------------
__global__ void k_front(const float* __restrict__ coord, const int* __restrict__ ids, int n,
                        int nb_scatter, const float* __restrict__ W2,
                        const float* __restrict__ dw_w, const float* __restrict__ dw_b,
                        const float* __restrict__ pw_W, const float* __restrict__ pw_b,
                        const float* __restrict__ b2) {
    int b = blockIdx.x;
    if (b < nb_scatter) {
        int i = b * 256 + threadIdx.x;
        if (i < n) {
            int p = ids[i];
            const float S = 4194304.0f;  // 2^22
            unsigned long long u0 = (unsigned long long)(coord[3 * i + 0] * S + 0.5f);
            unsigned long long u1 = (unsigned long long)(coord[3 * i + 1] * S + 0.5f);
            unsigned long long u2 = (unsigned long long)(coord[3 * i + 2] * S + 0.5f);
            atomicAdd(&g_s01[p], (u0 << 32) | u1);
            atomicAdd(&g_s2c[p], (u2 << 32) | 1ull);
        }
    } else {
        int t = (b - nb_scatter) * 256 + threadIdx.x;
        if (t >= DIM * DIM) return;
        int k = t >> 6, j = t & 63;
        g_AB[k * 128 + j] = dw_w[k] * pw_W[k * 64 + j];
        float s = 0.0f;
        for (int u = 0; u < 64; ++u)
            s += W2[k * 64 + u] * (dw_w[u] * pw_W[u * 64 + j]);
        g_AB[k * 128 + 64 + j] = s;
        if (k == 0) {
            float cv = pw_b[j];
            for (int u = 0; u < 64; ++u)
                cv += (b2[u] * dw_w[u] + dw_b[u]) * pw_W[u * 64 + j];
            g_cvec[j] = cv;
        }
    }
}

// ---------------- kernel 2: centers + re-zero ----------------
__global__ void k_centers() {
    int p = blockIdx.x * 256 + threadIdx.x;
    if (p >= PPATCH) return;
    unsigned long long a = g_s01[p], b = g_s2c[p];
    unsigned int cnt = (unsigned int)(b & 0xffffffffull);
    double d = (1.0 / 4194304.0) / (double)max(cnt, 1u);
    g_centers[p] = make_float4((float)((double)(a >> 32) * d),
                               (float)((double)(a & 0xffffffffull) * d),
                               (float)((double)(b >> 32) * d), 0.0f);
    g_s01[p] = 0ull;
    g_s2c[p] = 0ull;
}

// ---------------- kernel 3: main (warp-autonomous, HMMA everywhere) ----------------
// SMEM bytes:
//   WAH 0 (8K)  WAL 8192 (8K)  WBH 16384 (8K)  W1B 24576 (2K: 16k x 64n bf16, SW128)
//   b1s 26624(256) cvs 26880(256) lng 27136(256) lnb 27392(256)
//   per-warp @28672 + w*9216: XHI +0 (4K), XLO +4096 (4K), DLT +8192 (1K: 32 rows x 32B)
//   output staging overlays XHI..XLO (32 rows x 64 fp32 = 8K)
#define OWAH 0u
#define OWAL 8192u
#define OWBH 16384u
#define OW1B 24576u
#define OB1  26624u
#define OCV  26880u
#define OLNG 27136u
#define OLNB 27392u
#define OWRP 28672u
#define WSTRIDE 9216u
#define SMEM_BYTES (28672u + 8u * 9216u)   // 102400

__global__ void __launch_bounds__(NT, 2)
k_main(const float* __restrict__ x, const float* __restrict__ coord,
       const int* __restrict__ ids, const float* __restrict__ W1,
       const float* __restrict__ b1, const float* __restrict__ ln_g,
       const float* __restrict__ ln_b, float* __restrict__ out, int n, int ntiles) {
    extern __shared__ char smx[];
    const uint32_t sb = smem_u32(smx);
    int tid = threadIdx.x;
    int lane = tid & 31;
    int warp = tid >> 5;

    // ---- prologue ----
    float* b1s = (float*)(smx + OB1);
    float* cvs = (float*)(smx + OCV);
    float* lng = (float*)(smx + OLNG);
    float* lnb = (float*)(smx + OLNB);
    for (int i = tid; i < 64; i += NT) {
        b1s[i] = b1[i];
        cvs[i] = g_cvec[i];
        lng[i] = ln_g[i];
        lnb[i] = ln_b[i];
    }
    for (int i = tid; i < DIM * DIM; i += NT) {
        int k = i >> 6, j = i & 63;
        float fa = g_AB[k * 128 + j];
        float fb = g_AB[k * 128 + 64 + j];
        float fah = bfhi(fa);
        uint32_t off = swz((uint32_t)(k * 128 + j * 2));
        *(__nv_bfloat16*)(smx + OWAH + off) = __float2bfloat16_rn(fah);
        *(__nv_bfloat16*)(smx + OWAL + off) = __float2bfloat16_rn(fa - fah);
        *(__nv_bfloat16*)(smx + OWBH + off) = __float2bfloat16_rn(fb);
    }
    for (int i = tid; i < 16 * 64; i += NT) {
        int k = i >> 6, j = i & 63;
        float v = (k < 3) ? W1[k * 64 + j] : 0.0f;
        *(__nv_bfloat16*)(smx + OW1B + swz((uint32_t)(k * 128 + j * 2))) = __float2bfloat16_rn(v);
    }
    // zero delta tiles (k4..15 stay zero forever)
    for (int i = tid; i < 8 * 1024 / 4; i += NT) {
        int w = i / 256, o = i % 256;
        *(uint32_t*)(smx + OWRP + w * WSTRIDE + 8192u + o * 4) = 0u;
    }
    __syncthreads();

    const uint32_t XHIw = sb + OWRP + warp * WSTRIDE;
    const uint32_t XLOw = XHIw + 4096u;
    const uint32_t DLTw = XHIw + 8192u;
    float* stg = (float*)(smx + OWRP + warp * WSTRIDE);  // fp32 staging overlay, stride 64

    const int lm = lane & 15;
    const int lc = (lane >> 4) << 3;
    const int q2 = (lane & 3) * 2;
    const int rg = lane >> 2;

    const uint32_t WAHs = sb + OWAH, WALs = sb + OWAL, WBHs = sb + OWBH, W1Bs = sb + OW1B;

    for (int tile = blockIdx.x; tile < ntiles; tile += gridDim.x) {
        const int R = tile * TILE + warp * 32;  // this warp's first global row

        // ---- load x rows, split hi/lo, STS ----
#pragma unroll
        for (int i = 0; i < 16; ++i) {
            int r = i * 2 + (lane >> 4);        // local row 0..31
            int col = (lane & 15) * 4;
            float4 v = make_float4(0.f, 0.f, 0.f, 0.f);
            if (R + r < n) v = *(const float4*)&x[(size_t)(R + r) * 64 + col];
            float hx = bfhi(v.x), hy = bfhi(v.y), hz = bfhi(v.z), hw = bfhi(v.w);
            uint32_t off = swz((uint32_t)(r * 128 + (lane & 15) * 8));
            *(uint64_t*)(smx + (XHIw - sb) + off) = pack4bf(hx, hy, hz, hw);
            *(uint64_t*)(smx + (XLOw - sb) + off) = pack4bf(v.x - hx, v.y - hy, v.z - hz, v.w - hw);
        }

        // ---- delta for this lane's point -> DLT tile (32 rows x 32B, k0..3) ----
        {
            int pt = R + lane;
            float d0 = 0.f, d1 = 0.f, d2 = 0.f;
            if (pt < n) {
                float4 cc = g_centers[__ldg(&ids[pt])];
                d0 = __ldg(&coord[3 * pt + 0]) - cc.x;
                d1 = __ldg(&coord[3 * pt + 1]) - cc.y;
                d2 = __ldg(&coord[3 * pt + 2]) - cc.z;
            }
            *(uint64_t*)(smx + (DLTw - sb) + lane * 32) = pack4bf(d0, d1, d2, 0.f);
        }
        __syncwarp();

        // ---- MMA1: h = delta @ W1 + b1 (K=16 padded) ----
        float h[2][8][4];
#pragma unroll
        for (int nt = 0; nt < 8; ++nt) {
            float2 bb = *(float2*)&b1s[nt * 8 + q2];
#pragma unroll
            for (int mt = 0; mt < 2; ++mt) {
                h[mt][nt][0] = bb.x; h[mt][nt][1] = bb.y;
                h[mt][nt][2] = bb.x; h[mt][nt][3] = bb.y;
            }
        }
        uint32_t da[2][4];
#pragma unroll
        for (int mt = 0; mt < 2; ++mt)
            ldsm4(da[mt][0], da[mt][1], da[mt][2], da[mt][3],
                  DLTw + (uint32_t)(mt * 512 + (lane & 15) * 32 + (lane >> 4) * 16));
#pragma unroll
        for (int np = 0; np < 4; ++np) {
            uint32_t w0, w1r, w2, w3;
            ldsm4t(w0, w1r, w2, w3, W1Bs + swz((uint32_t)(lm * 128 + lc * 2 + np * 32)));
#pragma unroll
            for (int mt = 0; mt < 2; ++mt) {
                mma16816(h[mt][2 * np],     da[mt][0], da[mt][1], da[mt][2], da[mt][3], w0, w1r);
                mma16816(h[mt][2 * np + 1], da[mt][0], da[mt][1], da[mt][2], da[mt][3], w2, w3);
            }
        }

        // ---- GELU on fragments, pack to A-fragments for g @ B ----
        uint32_t ga[2][4][4];
#pragma unroll
        for (int mt = 0; mt < 2; ++mt)
#pragma unroll
            for (int kg = 0; kg < 4; ++kg) {
                float* e0 = h[mt][2 * kg];
                float* e1 = h[mt][2 * kg + 1];
                ga[mt][kg][0] = pack2bf(gelu_fast(e0[0]), gelu_fast(e0[1]));
                ga[mt][kg][1] = pack2bf(gelu_fast(e0[2]), gelu_fast(e0[3]));
                ga[mt][kg][2] = pack2bf(gelu_fast(e1[0]), gelu_fast(e1[1]));
                ga[mt][kg][3] = pack2bf(gelu_fast(e1[2]), gelu_fast(e1[3]));
            }

        // ---- main accumulators: out = x@A (split) + g@Bh + c ----
        float acc[2][8][4];
#pragma unroll
        for (int nt = 0; nt < 8; ++nt) {
            float2 cv = *(float2*)&cvs[nt * 8 + q2];
#pragma unroll
            for (int mt = 0; mt < 2; ++mt) {
                acc[mt][nt][0] = cv.x; acc[mt][nt][1] = cv.y;
                acc[mt][nt][2] = cv.x; acc[mt][nt][3] = cv.y;
            }
        }
#pragma unroll
        for (int kt = 0; kt < 4; ++kt) {
            uint32_t xh[2][4], xl[2][4];
#pragma unroll
            for (int mt = 0; mt < 2; ++mt) {
                uint32_t arow = swz((uint32_t)((mt * 16 + lm) * 128 + (kt * 16 + lc) * 2));
                ldsm4(xh[mt][0], xh[mt][1], xh[mt][2], xh[mt][3], XHIw + arow);
                ldsm4(xl[mt][0], xl[mt][1], xl[mt][2], xl[mt][3], XLOw + arow);
            }
#pragma unroll
            for (int np = 0; np < 4; ++np) {
                uint32_t brow = swz((uint32_t)((kt * 16 + lm) * 128 + lc * 2 + np * 32));
                uint32_t ah0, ah1, ah2, ah3, al0, al1, al2, al3, bh0, bh1, bh2, bh3;
                ldsm4t(ah0, ah1, ah2, ah3, WAHs + brow);
                ldsm4t(al0, al1, al2, al3, WALs + brow);
                ldsm4t(bh0, bh1, bh2, bh3, WBHs + brow);
#pragma unroll
                for (int mt = 0; mt < 2; ++mt) {
                    mma16816(acc[mt][2 * np],     xh[mt][0], xh[mt][1], xh[mt][2], xh[mt][3], ah0, ah1);
                    mma16816(acc[mt][2 * np + 1], xh[mt][0], xh[mt][1], xh[mt][2], xh[mt][3], ah2, ah3);
                    mma16816(acc[mt][2 * np],     xh[mt][0], xh[mt][1], xh[mt][2], xh[mt][3], al0, al1);
                    mma16816(acc[mt][2 * np + 1], xh[mt][0], xh[mt][1], xh[mt][2], xh[mt][3], al2, al3);
                    mma16816(acc[mt][2 * np],     xl[mt][0], xl[mt][1], xl[mt][2], xl[mt][3], bh0 * 0 + ah0, ah1);
                    mma16816(acc[mt][2 * np + 1], xl[mt][0], xl[mt][1], xl[mt][2], xl[mt][3], ah2, ah3);
                    mma16816(acc[mt][2 * np],     ga[mt][kt][0], ga[mt][kt][1], ga[mt][kt][2], ga[mt][kt][3], bh0, bh1);
                    mma16816(acc[mt][2 * np + 1], ga[mt][kt][0], ga[mt][kt][1], ga[mt][kt][2], ga[mt][kt][3], bh2, bh3);
                }
            }
        }
        __syncwarp();  // smem operand reads done; staging overlay may write

        // ---- LayerNorm + staging ----
#pragma unroll
        for (int mt = 0; mt < 2; ++mt) {
            float s0 = 0.f, s1 = 0.f, ss0 = 0.f, ss1 = 0.f;
#pragma unroll
            for (int nt = 0; nt < 8; ++nt) {
                float* a = acc[mt][nt];
                s0 += a[0] + a[1];
                ss0 += a[0] * a[0] + a[1] * a[1];
                s1 += a[2] + a[3];
                ss1 += a[2] * a[2] + a[3] * a[3];
            }
            s0 += __shfl_xor_sync(0xffffffffu, s0, 1);
            s0 += __shfl_xor_sync(0xffffffffu, s0, 2);
            ss0 += __shfl_xor_sync(0xffffffffu, ss0, 1);
            ss0 += __shfl_xor_sync(0xffffffffu, ss0, 2);
            s1 += __shfl_xor_sync(0xffffffffu, s1, 1);
            s1 += __shfl_xor_sync(0xffffffffu, s1, 2);
            ss1 += __shfl_xor_sync(0xffffffffu, ss1, 1);
            ss1 += __shfl_xor_sync(0xffffffffu, ss1, 2);
            float mu0 = s0 * 0.015625f, mu1 = s1 * 0.015625f;
            float r0v = rsqrtf(ss0 * 0.015625f - mu0 * mu0 + 1e-5f);
            float r1v = rsqrtf(ss1 * 0.015625f - mu1 * mu1 + 1e-5f);
            int r0 = mt * 16 + rg;      // local rows
            int r1 = r0 + 8;
#pragma unroll
            for (int nt = 0; nt < 8; ++nt) {
                int nn = nt * 8 + q2;
                float2 gg = *(float2*)&lng[nn];
                float2 bbv = *(float2*)&lnb[nn];
                float* a = acc[mt][nt];
                *(float2*)&stg[r0 * 64 + nn] =
                    make_float2((a[0] - mu0) * r0v * gg.x + bbv.x,
                                (a[1] - mu0) * r0v * gg.y + bbv.y);
                *(float2*)&stg[r1 * 64 + nn] =
                    make_float2((a[2] - mu1) * r1v * gg.x + bbv.x,
                                (a[3] - mu1) * r1v * gg.y + bbv.y);
            }
        }
        __syncwarp();

        // ---- coalesced store of this warp's 32 rows ----
#pragma unroll
        for (int i = 0; i < 16; ++i) {
            int r = i * 2 + (lane >> 4);
            int col = (lane & 15) * 4;
            if (R + r < n)
                *(float4*)&out[(size_t)(R + r) * 64 + col] = *(const float4*)&stg[r * 64 + col];
        }
        __syncwarp();  // staging region reused as operand buffer next tile
    }
}

// ---------------- launch ----------------
extern "C" void kernel_launch(void* const* d_in, const int* in_sizes, int n_in,
                              void* d_out, int out_size) {
    const float* x     = (const float*)d_in[0];
    const float* coord = (const float*)d_in[1];
    const int*   ids   = (const int*)d_in[2];
    const float* W1    = (const float*)d_in[3];
    const float* b1    = (const float*)d_in[4];
    const float* W2    = (const float*)d_in[5];
    const float* b2    = (const float*)d_in[6];
    const float* dw_w  = (const float*)d_in[7];
    const float* dw_b  = (const float*)d_in[8];
    const float* pw_W  = (const float*)d_in[9];
    const float* pw_b  = (const float*)d_in[10];
    const float* ln_g  = (const float*)d_in[11];
    const float* ln_b  = (const float*)d_in[12];
    float* out = (float*)d_out;

    int n = in_sizes[0] / DIM;
    int nbs = (n + 255) / 256;

    k_front<<<nbs + 16, 256>>>(coord, ids, n, nbs, W2, dw_w, dw_b, pw_W, pw_b, b2);
    k_centers<<<16, 256>>>();

    int ntiles = (n + TILE - 1) / TILE;
    cudaFuncSetAttribute(k_main, cudaFuncAttributeMaxDynamicSharedMemorySize, SMEM_BYTES);
    k_main<<<296, NT, SMEM_BYTES>>>(x, coord, ids, W1, b1, ln_g, ln_b, out, n, ntiles);
}

// round 5
// speedup vs baseline: 4.1424x; 1.4101x over previous
#include <cuda_runtime.h>
#include <cuda_bf16.h>
#include <math.h>
#include <stdint.h>

#define DIM 64
#define PPATCH 4096
#define TILE 256
#define NT 256
#define NREP 8

// ---------------- device scratch ----------------
__device__ unsigned long long g_s01[NREP * PPATCH];
__device__ unsigned long long g_s2c[NREP * PPATCH];
__device__ float4             g_centers[PPATCH];
__device__ float              g_AB[DIM * 128]; // row k: [0..63]=A[k][:], [64..127]=B[k][:]
__device__ float              g_cvec[DIM];

// ---------------- helpers ----------------
__device__ __forceinline__ uint32_t smem_u32(const void* p) {
    uint32_t a;
    asm("{ .reg .u64 t; cvta.to.shared.u64 t, %1; cvt.u32.u64 %0, t; }" : "=r"(a) : "l"(p));
    return a;
}
__device__ __forceinline__ uint32_t swz(uint32_t x) { return x ^ ((x >> 3) & 0x70); }

__device__ __forceinline__ void ldsm4(uint32_t &r0, uint32_t &r1, uint32_t &r2, uint32_t &r3,
                                      uint32_t addr) {
    asm volatile("ldmatrix.sync.aligned.m8n8.x4.shared.b16 {%0,%1,%2,%3}, [%4];"
                 : "=r"(r0), "=r"(r1), "=r"(r2), "=r"(r3) : "r"(addr));
}
__device__ __forceinline__ void ldsm4t(uint32_t &r0, uint32_t &r1, uint32_t &r2, uint32_t &r3,
                                       uint32_t addr) {
    asm volatile("ldmatrix.sync.aligned.m8n8.x4.trans.shared.b16 {%0,%1,%2,%3}, [%4];"
                 : "=r"(r0), "=r"(r1), "=r"(r2), "=r"(r3) : "r"(addr));
}
__device__ __forceinline__ void mma16816(float (&d)[4], uint32_t a0, uint32_t a1, uint32_t a2,
                                         uint32_t a3, uint32_t b0, uint32_t b1) {
    asm volatile(
        "mma.sync.aligned.m16n8k16.row.col.f32.bf16.bf16.f32 "
        "{%0,%1,%2,%3}, {%4,%5,%6,%7}, {%8,%9}, {%0,%1,%2,%3};"
        : "+f"(d[0]), "+f"(d[1]), "+f"(d[2]), "+f"(d[3])
        : "r"(a0), "r"(a1), "r"(a2), "r"(a3), "r"(b0), "r"(b1));
}

__device__ __forceinline__ uint32_t pack2bf(float a, float b) {
    __nv_bfloat162 p = __floats2bfloat162_rn(a, b);
    return *reinterpret_cast<uint32_t*>(&p);
}
__device__ __forceinline__ uint64_t pack4bf(float a, float b, float c, float d) {
    return (uint64_t)pack2bf(a, b) | ((uint64_t)pack2bf(c, d) << 32);
}
// truncation split: hi = bits & 0xffff0000 (exact bf16), lo = v - hi (fits bf16 to ~2^-16 total)
__device__ __forceinline__ uint32_t hipack(float2 v) {   // bf16x2 of truncated highs
    return __byte_perm(__float_as_uint(v.x), __float_as_uint(v.y), 0x7632);
}
__device__ __forceinline__ uint32_t lopack(float2 v) {
    float hx = __uint_as_float(__float_as_uint(v.x) & 0xffff0000u);
    float hy = __uint_as_float(__float_as_uint(v.y) & 0xffff0000u);
    return pack2bf(v.x - hx, v.y - hy);
}
// GELU tanh-form with HW tanh: 0.5h(1+tanh(0.79788456(h+0.044715h^3)))
__device__ __forceinline__ float gelu_fast(float h) {
    float p = h * h;
    float y = h * fmaf(0.0356774081f, p, 0.7978845608f);
    float t;
    asm("tanh.approx.f32 %0, %1;" : "=f"(t) : "f"(y));
    float hh = 0.5f * h;
    return fmaf(hh, t, hh);
}

// ---------------- kernel 1: scatter (replicated accumulators) + weight fold ----------------
__global__ void k_front(const float* __restrict__ coord, const int* __restrict__ ids, int n,
                        int nb_scatter, const float* __restrict__ W2,
                        const float* __restrict__ dw_w, const float* __restrict__ dw_b,
                        const float* __restrict__ pw_W, const float* __restrict__ pw_b,
                        const float* __restrict__ b2) {
    int b = blockIdx.x;
    if (b < nb_scatter) {
        int i = b * 256 + threadIdx.x;
        if (i < n) {
            int p = ids[i] + (b & (NREP - 1)) * PPATCH;
            const float S = 4194304.0f;  // 2^22
            unsigned long long u0 = (unsigned long long)(coord[3 * i + 0] * S + 0.5f);
            unsigned long long u1 = (unsigned long long)(coord[3 * i + 1] * S + 0.5f);
            unsigned long long u2 = (unsigned long long)(coord[3 * i + 2] * S + 0.5f);
            atomicAdd(&g_s01[p], (u0 << 32) | u1);
            atomicAdd(&g_s2c[p], (u2 << 32) | 1ull);
        }
    } else {
        int t = (b - nb_scatter) * 256 + threadIdx.x;
        if (t >= DIM * DIM) return;
        int k = t >> 6, j = t & 63;
        g_AB[k * 128 + j] = dw_w[k] * pw_W[k * 64 + j];
        float s = 0.0f;
        for (int u = 0; u < 64; ++u)
            s += W2[k * 64 + u] * (dw_w[u] * pw_W[u * 64 + j]);
        g_AB[k * 128 + 64 + j] = s;
        if (k == 0) {
            float cv = pw_b[j];
            for (int u = 0; u < 64; ++u)
                cv += (b2[u] * dw_w[u] + dw_b[u]) * pw_W[u * 64 + j];
            g_cvec[j] = cv;
        }
    }
}

// ---------------- kernel 2: centers from replicas + re-zero ----------------
__global__ void k_centers() {
    int p = blockIdx.x * 256 + threadIdx.x;
    if (p >= PPATCH) return;
    unsigned long long a = 0ull, b = 0ull;
#pragma unroll
    for (int r = 0; r < NREP; ++r) {
        a += g_s01[r * PPATCH + p];
        b += g_s2c[r * PPATCH + p];
        g_s01[r * PPATCH + p] = 0ull;
        g_s2c[r * PPATCH + p] = 0ull;
    }
    unsigned int cnt = (unsigned int)(b & 0xffffffffull);
    double d = (1.0 / 4194304.0) / (double)max(cnt, 1u);
    g_centers[p] = make_float4((float)((double)(a >> 32) * d),
                               (float)((double)(a & 0xffffffffull) * d),
                               (float)((double)(b >> 32) * d), 0.0f);
}

// ---------------- kernel 3: main (x and out stay in registers/GMEM) ----------------
// SMEM bytes:
//   WAH 0 (8K)  WAL 8192 (8K)  WBH 16384 (8K)  W1B 24576 (2K)
//   b1s 26624(256) cvs 26880(256) lng 27136(256) lnb 27392(256)
//   DLT per warp @27648 + w*1024 (32 rows x 32B)
#define OWAH 0u
#define OWAL 8192u
#define OWBH 16384u
#define OW1B 24576u
#define OB1  26624u
#define OCV  26880u
#define OLNG 27136u
#define OLNB 27392u
#define ODLT 27648u
#define SMEM_BYTES (27648u + 8u * 1024u)   // 35840

__global__ void __launch_bounds__(NT, 2)
k_main(const float* __restrict__ x, const float* __restrict__ coord,
       const int* __restrict__ ids, const float* __restrict__ W1,
       const float* __restrict__ b1, const float* __restrict__ ln_g,
       const float* __restrict__ ln_b, float* __restrict__ out, int n, int ntiles) {
    extern __shared__ char smx[];
    const uint32_t sb = smem_u32(smx);
    int tid = threadIdx.x;
    int lane = tid & 31;
    int warp = tid >> 5;

    // ---- prologue ----
    float* b1s = (float*)(smx + OB1);
    float* cvs = (float*)(smx + OCV);
    float* lng = (float*)(smx + OLNG);
    float* lnb = (float*)(smx + OLNB);
    for (int i = tid; i < 64; i += NT) {
        b1s[i] = b1[i];
        cvs[i] = g_cvec[i];
        lng[i] = ln_g[i];
        lnb[i] = ln_b[i];
    }
    for (int i = tid; i < DIM * DIM; i += NT) {
        int k = i >> 6, j = i & 63;
        float fa = g_AB[k * 128 + j];
        float fb = g_AB[k * 128 + 64 + j];
        float fah = __uint_as_float(__float_as_uint(fa) & 0xffff0000u);  // trunc split
        uint32_t off = swz((uint32_t)(k * 128 + j * 2));
        *(__nv_bfloat16*)(smx + OWAH + off) = __float2bfloat16_rn(fah);
        *(__nv_bfloat16*)(smx + OWAL + off) = __float2bfloat16_rn(fa - fah);
        *(__nv_bfloat16*)(smx + OWBH + off) = __float2bfloat16_rn(fb);
    }
    for (int i = tid; i < 16 * 64; i += NT) {
        int k = i >> 6, j = i & 63;
        float v = (k < 3) ? W1[k * 64 + j] : 0.0f;
        *(__nv_bfloat16*)(smx + OW1B + swz((uint32_t)(k * 128 + j * 2))) = __float2bfloat16_rn(v);
    }
    // zero delta tiles (cols 4..15 remain zero forever)
    for (int i = tid; i < 8 * 256; i += NT) {
        int w = i >> 8, o = i & 255;
        *(uint32_t*)(smx + ODLT + w * 1024u + o * 4) = 0u;
    }
    __syncthreads();

    const uint32_t DLTw = sb + ODLT + warp * 1024u;
    const uint32_t WAHs = sb + OWAH, WALs = sb + OWAL, WBHs = sb + OWBH, W1Bs = sb + OW1B;

    const int lm = lane & 15;
    const int lc = (lane >> 4) << 3;
    const int q2 = (lane & 3) * 2;
    const int rg = lane >> 2;

    // x fragment addressing: lane reads rows mt*16 + rg (+8), cols kt*16 + q2 (+8)
    for (int tile = blockIdx.x; tile < ntiles; tile += gridDim.x) {
        const int R = tile * TILE + warp * 32;

        // ---- issue raw x loads for kt=0 early (hidden under front MLP) ----
        float2 raw[2][8];
#pragma unroll
        for (int mt = 0; mt < 2; ++mt)
#pragma unroll
            for (int ro = 0; ro < 2; ++ro)
#pragma unroll
                for (int co = 0; co < 2; ++co) {
                    int r = R + mt * 16 + ro * 8 + rg;
                    float2 v = make_float2(0.f, 0.f);
                    if (r < n) v = *(const float2*)&x[(size_t)r * 64 + q2 + co * 8];
                    raw[0][mt * 4 + ro * 2 + co] = v;
                }

        // ---- delta for this lane's point ----
        {
            int pt = R + lane;
            float d0 = 0.f, d1 = 0.f, d2 = 0.f;
            if (pt < n) {
                float4 cc = g_centers[__ldg(&ids[pt])];
                d0 = __ldg(&coord[3 * pt + 0]) - cc.x;
                d1 = __ldg(&coord[3 * pt + 1]) - cc.y;
                d2 = __ldg(&coord[3 * pt + 2]) - cc.z;
            }
            *(uint64_t*)(smx + (DLTw - sb) + lane * 32) = pack4bf(d0, d1, d2, 0.f);
        }
        __syncwarp();

        // ---- MMA1: h = delta @ W1 + b1 ----
        float h[2][8][4];
#pragma unroll
        for (int nt = 0; nt < 8; ++nt) {
            float2 bb = *(float2*)&b1s[nt * 8 + q2];
#pragma unroll
            for (int mt = 0; mt < 2; ++mt) {
                h[mt][nt][0] = bb.x; h[mt][nt][1] = bb.y;
                h[mt][nt][2] = bb.x; h[mt][nt][3] = bb.y;
            }
        }
        {
            uint32_t da[2][4];
#pragma unroll
            for (int mt = 0; mt < 2; ++mt)
                ldsm4(da[mt][0], da[mt][1], da[mt][2], da[mt][3],
                      DLTw + (uint32_t)(mt * 512 + lm * 32 + (lane >> 4) * 16));
#pragma unroll
            for (int np = 0; np < 4; ++np) {
                uint32_t w0, w1r, w2, w3;
                ldsm4t(w0, w1r, w2, w3, W1Bs + swz((uint32_t)(lm * 128 + lc * 2 + np * 32)));
#pragma unroll
                for (int mt = 0; mt < 2; ++mt) {
                    mma16816(h[mt][2 * np],     da[mt][0], da[mt][1], da[mt][2], da[mt][3], w0, w1r);
                    mma16816(h[mt][2 * np + 1], da[mt][0], da[mt][1], da[mt][2], da[mt][3], w2, w3);
                }
            }
        }

        // ---- GELU -> g A-fragments ----
        uint32_t ga[2][4][4];
#pragma unroll
        for (int mt = 0; mt < 2; ++mt)
#pragma unroll
            for (int kg = 0; kg < 4; ++kg) {
                float* e0 = h[mt][2 * kg];
                float* e1 = h[mt][2 * kg + 1];
                ga[mt][kg][0] = pack2bf(gelu_fast(e0[0]), gelu_fast(e0[1]));
                ga[mt][kg][1] = pack2bf(gelu_fast(e0[2]), gelu_fast(e0[3]));
                ga[mt][kg][2] = pack2bf(gelu_fast(e1[0]), gelu_fast(e1[1]));
                ga[mt][kg][3] = pack2bf(gelu_fast(e1[2]), gelu_fast(e1[3]));
            }

        // ---- acc init with bias ----
        float acc[2][8][4];
#pragma unroll
        for (int nt = 0; nt < 8; ++nt) {
            float2 cv = *(float2*)&cvs[nt * 8 + q2];
#pragma unroll
            for (int mt = 0; mt < 2; ++mt) {
                acc[mt][nt][0] = cv.x; acc[mt][nt][1] = cv.y;
                acc[mt][nt][2] = cv.x; acc[mt][nt][3] = cv.y;
            }
        }

        // ---- phase A: acc += g @ Bh (frees ga afterwards) ----
#pragma unroll
        for (int kt = 0; kt < 4; ++kt)
#pragma unroll
            for (int np = 0; np < 4; ++np) {
                uint32_t b0, b1r, b2, b3;
                ldsm4t(b0, b1r, b2, b3,
                       WBHs + swz((uint32_t)((kt * 16 + lm) * 128 + lc * 2 + np * 32)));
#pragma unroll
                for (int mt = 0; mt < 2; ++mt) {
                    mma16816(acc[mt][2 * np],     ga[mt][kt][0], ga[mt][kt][1],
                             ga[mt][kt][2], ga[mt][kt][3], b0, b1r);
                    mma16816(acc[mt][2 * np + 1], ga[mt][kt][0], ga[mt][kt][1],
                             ga[mt][kt][2], ga[mt][kt][3], b2, b3);
                }
            }

        // ---- phase B: acc += xh@(Ah+Al) + xl@Ah, kt-streamed with reg prefetch ----
#pragma unroll
        for (int kt = 0; kt < 4; ++kt) {
            // prefetch raw for kt+1
            if (kt < 3) {
#pragma unroll
                for (int mt = 0; mt < 2; ++mt)
#pragma unroll
                    for (int ro = 0; ro < 2; ++ro)
#pragma unroll
                        for (int co = 0; co < 2; ++co) {
                            int r = R + mt * 16 + ro * 8 + rg;
                            float2 v = make_float2(0.f, 0.f);
                            if (r < n)
                                v = *(const float2*)&x[(size_t)r * 64 + (kt + 1) * 16 + q2 + co * 8];
                            raw[(kt + 1) & 1][mt * 4 + ro * 2 + co] = v;
                        }
            }
            // build fragments for kt
            uint32_t xh[2][4], xl[2][4];
#pragma unroll
            for (int mt = 0; mt < 2; ++mt) {
                float2* rw = &raw[kt & 1][mt * 4];
                xh[mt][0] = hipack(rw[0]); xl[mt][0] = lopack(rw[0]);  // (r, c)
                xh[mt][1] = hipack(rw[2]); xl[mt][1] = lopack(rw[2]);  // (r+8, c)
                xh[mt][2] = hipack(rw[1]); xl[mt][2] = lopack(rw[1]);  // (r, c+8)
                xh[mt][3] = hipack(rw[3]); xl[mt][3] = lopack(rw[3]);  // (r+8, c+8)
            }
#pragma unroll
            for (int np = 0; np < 4; ++np) {
                uint32_t brow = swz((uint32_t)((kt * 16 + lm) * 128 + lc * 2 + np * 32));
                uint32_t ah0, ah1, ah2, ah3, al0, al1, al2, al3;
                ldsm4t(ah0, ah1, ah2, ah3, WAHs + brow);
                ldsm4t(al0, al1, al2, al3, WALs + brow);
#pragma unroll
                for (int mt = 0; mt < 2; ++mt) {
                    mma16816(acc[mt][2 * np],     xh[mt][0], xh[mt][1], xh[mt][2], xh[mt][3], ah0, ah1);
                    mma16816(acc[mt][2 * np + 1], xh[mt][0], xh[mt][1], xh[mt][2], xh[mt][3], ah2, ah3);
                    mma16816(acc[mt][2 * np],     xh[mt][0], xh[mt][1], xh[mt][2], xh[mt][3], al0, al1);
                    mma16816(acc[mt][2 * np + 1], xh[mt][0], xh[mt][1], xh[mt][2], xh[mt][3], al2, al3);
                    mma16816(acc[mt][2 * np],     xl[mt][0], xl[mt][1], xl[mt][2], xl[mt][3], ah0, ah1);
                    mma16816(acc[mt][2 * np + 1], xl[mt][0], xl[mt][1], xl[mt][2], xl[mt][3], ah2, ah3);
                }
            }
        }

        // ---- LayerNorm + direct STG in fragment layout ----
#pragma unroll
        for (int mt = 0; mt < 2; ++mt) {
            float s0 = 0.f, s1 = 0.f, ss0 = 0.f, ss1 = 0.f;
#pragma unroll
            for (int nt = 0; nt < 8; ++nt) {
                float* a = acc[mt][nt];
                s0 += a[0] + a[1];
                ss0 += a[0] * a[0] + a[1] * a[1];
                s1 += a[2] + a[3];
                ss1 += a[2] * a[2] + a[3] * a[3];
            }
            s0 += __shfl_xor_sync(0xffffffffu, s0, 1);
            s0 += __shfl_xor_sync(0xffffffffu, s0, 2);
            ss0 += __shfl_xor_sync(0xffffffffu, ss0, 1);
            ss0 += __shfl_xor_sync(0xffffffffu, ss0, 2);
            s1 += __shfl_xor_sync(0xffffffffu, s1, 1);
            s1 += __shfl_xor_sync(0xffffffffu, s1, 2);
            ss1 += __shfl_xor_sync(0xffffffffu, ss1, 1);
            ss1 += __shfl_xor_sync(0xffffffffu, ss1, 2);
            float mu0 = s0 * 0.015625f, mu1 = s1 * 0.015625f;
            float r0v = rsqrtf(ss0 * 0.015625f - mu0 * mu0 + 1e-5f);
            float r1v = rsqrtf(ss1 * 0.015625f - mu1 * mu1 + 1e-5f);
            int r0 = R + mt * 16 + rg;
            int r1 = r0 + 8;
#pragma unroll
            for (int nt = 0; nt < 8; ++nt) {
                int nn = nt * 8 + q2;
                float2 gg = *(float2*)&lng[nn];
                float2 bbv = *(float2*)&lnb[nn];
                float* a = acc[mt][nt];
                if (r0 < n)
                    *(float2*)&out[(size_t)r0 * 64 + nn] =
                        make_float2((a[0] - mu0) * r0v * gg.x + bbv.x,
                                    (a[1] - mu0) * r0v * gg.y + bbv.y);
                if (r1 < n)
                    *(float2*)&out[(size_t)r1 * 64 + nn] =
                        make_float2((a[2] - mu1) * r1v * gg.x + bbv.x,
                                    (a[3] - mu1) * r1v * gg.y + bbv.y);
            }
        }
        __syncwarp();  // DLT reuse next tile
    }
}

// ---------------- launch ----------------
extern "C" void kernel_launch(void* const* d_in, const int* in_sizes, int n_in,
                              void* d_out, int out_size) {
    const float* x     = (const float*)d_in[0];
    const float* coord = (const float*)d_in[1];
    const int*   ids   = (const int*)d_in[2];
    const float* W1    = (const float*)d_in[3];
    const float* b1    = (const float*)d_in[4];
    const float* W2    = (const float*)d_in[5];
    const float* b2    = (const float*)d_in[6];
    const float* dw_w  = (const float*)d_in[7];
    const float* dw_b  = (const float*)d_in[8];
    const float* pw_W  = (const float*)d_in[9];
    const float* pw_b  = (const float*)d_in[10];
    const float* ln_g  = (const float*)d_in[11];
    const float* ln_b  = (const float*)d_in[12];
    float* out = (float*)d_out;

    int n = in_sizes[0] / DIM;
    int nbs = (n + 255) / 256;

    k_front<<<nbs + 16, 256>>>(coord, ids, n, nbs, W2, dw_w, dw_b, pw_W, pw_b, b2);
    k_centers<<<16, 256>>>();

    int ntiles = (n + TILE - 1) / TILE;
    cudaFuncSetAttribute(k_main, cudaFuncAttributeMaxDynamicSharedMemorySize, SMEM_BYTES);
    k_main<<<296, NT, SMEM_BYTES>>>(x, coord, ids, W1, b1, ln_g, ln_b, out, n, ntiles);
}

// round 6
// speedup vs baseline: 4.7458x; 1.1457x over previous
#include <cuda_runtime.h>
#include <cuda_fp16.h>
#include <math.h>
#include <stdint.h>

#define DIM 64
#define PPATCH 4096
#define TILE 256
#define NT 256
#define NREP 16

// ---------------- device scratch ----------------
__device__ unsigned long long g_s01[NREP * PPATCH];
__device__ unsigned long long g_s2c[NREP * PPATCH];
__device__ float4             g_centers[PPATCH];
__device__ float              g_AB[DIM * 128]; // row k: [0..63]=A[k][:], [64..127]=B[k][:]
__device__ float              g_cvec[DIM];

// ---------------- helpers ----------------
__device__ __forceinline__ uint32_t smem_u32(const void* p) {
    uint32_t a;
    asm("{ .reg .u64 t; cvta.to.shared.u64 t, %1; cvt.u32.u64 %0, t; }" : "=r"(a) : "l"(p));
    return a;
}
__device__ __forceinline__ uint32_t swz(uint32_t x) { return x ^ ((x >> 3) & 0x70); }

__device__ __forceinline__ void ldsm4(uint32_t &r0, uint32_t &r1, uint32_t &r2, uint32_t &r3,
                                      uint32_t addr) {
    asm volatile("ldmatrix.sync.aligned.m8n8.x4.shared.b16 {%0,%1,%2,%3}, [%4];"
                 : "=r"(r0), "=r"(r1), "=r"(r2), "=r"(r3) : "r"(addr));
}
__device__ __forceinline__ void ldsm4t(uint32_t &r0, uint32_t &r1, uint32_t &r2, uint32_t &r3,
                                       uint32_t addr) {
    asm volatile("ldmatrix.sync.aligned.m8n8.x4.trans.shared.b16 {%0,%1,%2,%3}, [%4];"
                 : "=r"(r0), "=r"(r1), "=r"(r2), "=r"(r3) : "r"(addr));
}
__device__ __forceinline__ void mma16816(float (&d)[4], uint32_t a0, uint32_t a1, uint32_t a2,
                                         uint32_t a3, uint32_t b0, uint32_t b1) {
    asm volatile(
        "mma.sync.aligned.m16n8k16.row.col.f32.f16.f16.f32 "
        "{%0,%1,%2,%3}, {%4,%5,%6,%7}, {%8,%9}, {%0,%1,%2,%3};"
        : "+f"(d[0]), "+f"(d[1]), "+f"(d[2]), "+f"(d[3])
        : "r"(a0), "r"(a1), "r"(a2), "r"(a3), "r"(b0), "r"(b1));
}

__device__ __forceinline__ uint32_t packh2(float a, float b) {
    __half2 p = __floats2half2_rn(a, b);
    return *reinterpret_cast<uint32_t*>(&p);
}
__device__ __forceinline__ uint64_t pack4h(float a, float b, float c, float d) {
    return (uint64_t)packh2(a, b) | ((uint64_t)packh2(c, d) << 32);
}
// fp16 split of a float2: hi = rn(v), lo = rn(v - hi)
__device__ __forceinline__ void splith2(float2 v, uint32_t &hi, uint32_t &lo) {
    __half hx = __float2half_rn(v.x);
    __half hy = __float2half_rn(v.y);
    __half2 h = __halves2half2(hx, hy);
    hi = *reinterpret_cast<uint32_t*>(&h);
    lo = packh2(v.x - __half2float(hx), v.y - __half2float(hy));
}
// GELU tanh-form with HW tanh
__device__ __forceinline__ float gelu_fast(float h) {
    float p = h * h;
    float y = h * fmaf(0.0356774081f, p, 0.7978845608f);
    float t;
    asm("tanh.approx.f32 %0, %1;" : "=f"(t) : "f"(y));
    float hh = 0.5f * h;
    return fmaf(hh, t, hh);
}

// ---------------- kernel 0: no-op (ncu launch-index steering) ----------------
__global__ void k_noop() {}

// ---------------- kernel 1: scatter (coalesced coord, replicated acc) + weight fold ----------------
__global__ void k_front(const float* __restrict__ coord, const int* __restrict__ ids, int n,
                        int nb_scatter, const float* __restrict__ W2,
                        const float* __restrict__ dw_w, const float* __restrict__ dw_b,
                        const float* __restrict__ pw_W, const float* __restrict__ pw_b,
                        const float* __restrict__ b2) {
    __shared__ float cs[768];
    int b = blockIdx.x;
    if (b < nb_scatter) {
        int base = b * 256;
        for (int j = threadIdx.x; j < 768; j += 256) {
            int idx = base * 3 + j;
            cs[j] = (idx < 3 * n) ? coord[idx] : 0.0f;
        }
        __syncthreads();
        int i = base + threadIdx.x;
        if (i < n) {
            int t = threadIdx.x;
            int p = ids[i] + (b & (NREP - 1)) * PPATCH;
            const float S = 4194304.0f;  // 2^22
            unsigned long long u0 = (unsigned long long)(cs[3 * t + 0] * S + 0.5f);
            unsigned long long u1 = (unsigned long long)(cs[3 * t + 1] * S + 0.5f);
            unsigned long long u2 = (unsigned long long)(cs[3 * t + 2] * S + 0.5f);
            atomicAdd(&g_s01[p], (u0 << 32) | u1);
            atomicAdd(&g_s2c[p], (u2 << 32) | 1ull);
        }
    } else {
        int t = (b - nb_scatter) * 256 + threadIdx.x;
        if (t >= DIM * DIM) return;
        int k = t >> 6, j = t & 63;
        g_AB[k * 128 + j] = dw_w[k] * pw_W[k * 64 + j];
        float s = 0.0f;
        for (int u = 0; u < 64; ++u)
            s += W2[k * 64 + u] * (dw_w[u] * pw_W[u * 64 + j]);
        g_AB[k * 128 + 64 + j] = s;
        if (k == 0) {
            float cv = pw_b[j];
            for (int u = 0; u < 64; ++u)
                cv += (b2[u] * dw_w[u] + dw_b[u]) * pw_W[u * 64 + j];
            g_cvec[j] = cv;
        }
    }
}

// ---------------- kernel 2: centers from replicas + re-zero ----------------
__global__ void k_centers() {
    int p = blockIdx.x * 256 + threadIdx.x;
    if (p >= PPATCH) return;
    unsigned long long a = 0ull, b = 0ull;
#pragma unroll
    for (int r = 0; r < NREP; ++r) {
        a += g_s01[r * PPATCH + p];
        b += g_s2c[r * PPATCH + p];
        g_s01[r * PPATCH + p] = 0ull;
        g_s2c[r * PPATCH + p] = 0ull;
    }
    unsigned int cnt = (unsigned int)(b & 0xffffffffull);
    double d = (1.0 / 4194304.0) / (double)max(cnt, 1u);
    g_centers[p] = make_float4((float)((double)(a >> 32) * d),
                               (float)((double)(a & 0xffffffffull) * d),
                               (float)((double)(b >> 32) * d), 0.0f);
}

// ---------------- kernel 3: main (fp16 MMA, 2-product x split) ----------------
// SMEM bytes:
//   WAF 0 (8K)  WBF 8192 (8K)  W1F 16384 (2K)
//   b1s 18432(256) cvs 18688(256) lng 18944(256) lnb 19200(256)
//   DLT per warp @19456 + w*1024 (32 rows x 32B)
#define OWAF 0u
#define OWBF 8192u
#define OW1F 16384u
#define OB1  18432u
#define OCV  18688u
#define OLNG 18944u
#define OLNB 19200u
#define ODLT 19456u
#define SMEM_BYTES (19456u + 8u * 1024u)   // 27648

__global__ void __launch_bounds__(NT, 2)
k_main(const float* __restrict__ x, const float* __restrict__ coord,
       const int* __restrict__ ids, const float* __restrict__ W1,
       const float* __restrict__ b1, const float* __restrict__ ln_g,
       const float* __restrict__ ln_b, float* __restrict__ out, int n, int ntiles) {
    extern __shared__ char smx[];
    const uint32_t sb = smem_u32(smx);
    int tid = threadIdx.x;
    int lane = tid & 31;
    int warp = tid >> 5;

    // ---- prologue ----
    float* b1s = (float*)(smx + OB1);
    float* cvs = (float*)(smx + OCV);
    float* lng = (float*)(smx + OLNG);
    float* lnb = (float*)(smx + OLNB);
    for (int i = tid; i < 64; i += NT) {
        b1s[i] = b1[i];
        cvs[i] = g_cvec[i];
        lng[i] = ln_g[i];
        lnb[i] = ln_b[i];
    }
    for (int i = tid; i < DIM * DIM; i += NT) {
        int k = i >> 6, j = i & 63;
        uint32_t off = swz((uint32_t)(k * 128 + j * 2));
        *(__half*)(smx + OWAF + off) = __float2half_rn(g_AB[k * 128 + j]);
        *(__half*)(smx + OWBF + off) = __float2half_rn(g_AB[k * 128 + 64 + j]);
    }
    for (int i = tid; i < 16 * 64; i += NT) {
        int k = i >> 6, j = i & 63;
        float v = (k < 3) ? W1[k * 64 + j] : 0.0f;
        *(__half*)(smx + OW1F + swz((uint32_t)(k * 128 + j * 2))) = __float2half_rn(v);
    }
    // zero delta tiles (cols 4..15 remain zero forever)
    for (int i = tid; i < 8 * 256; i += NT) {
        int w = i >> 8, o = i & 255;
        *(uint32_t*)(smx + ODLT + w * 1024u + o * 4) = 0u;
    }
    __syncthreads();

    const uint32_t DLTw = sb + ODLT + warp * 1024u;
    const uint32_t WAFs = sb + OWAF, WBFs = sb + OWBF, W1Fs = sb + OW1F;

    const int lm = lane & 15;
    const int lc = (lane >> 4) << 3;
    const int q2 = (lane & 3) * 2;
    const int rg = lane >> 2;

    for (int tile = blockIdx.x; tile < ntiles; tile += gridDim.x) {
        const int R = tile * TILE + warp * 32;

        // ---- issue raw x loads for kt=0 (hidden under front MLP) ----
        float2 raw[2][8];
#pragma unroll
        for (int mt = 0; mt < 2; ++mt)
#pragma unroll
            for (int ro = 0; ro < 2; ++ro)
#pragma unroll
                for (int co = 0; co < 2; ++co) {
                    int r = R + mt * 16 + ro * 8 + rg;
                    float2 v = make_float2(0.f, 0.f);
                    if (r < n) v = *(const float2*)&x[(size_t)r * 64 + q2 + co * 8];
                    raw[0][mt * 4 + ro * 2 + co] = v;
                }

        // ---- delta for this lane's point ----
        {
            int pt = R + lane;
            float d0 = 0.f, d1 = 0.f, d2 = 0.f;
            if (pt < n) {
                float4 cc = g_centers[__ldg(&ids[pt])];
                d0 = __ldg(&coord[3 * pt + 0]) - cc.x;
                d1 = __ldg(&coord[3 * pt + 1]) - cc.y;
                d2 = __ldg(&coord[3 * pt + 2]) - cc.z;
            }
            *(uint64_t*)(smx + (DLTw - sb) + lane * 32) = pack4h(d0, d1, d2, 0.f);
        }
        __syncwarp();

        // ---- MMA1: h = delta @ W1 + b1 (acc array reused later as main acc) ----
        float acc[2][8][4];
#pragma unroll
        for (int nt = 0; nt < 8; ++nt) {
            float2 bb = *(float2*)&b1s[nt * 8 + q2];
#pragma unroll
            for (int mt = 0; mt < 2; ++mt) {
                acc[mt][nt][0] = bb.x; acc[mt][nt][1] = bb.y;
                acc[mt][nt][2] = bb.x; acc[mt][nt][3] = bb.y;
            }
        }
        {
            uint32_t da[2][4];
#pragma unroll
            for (int mt = 0; mt < 2; ++mt)
                ldsm4(da[mt][0], da[mt][1], da[mt][2], da[mt][3],
                      DLTw + (uint32_t)(mt * 512 + lm * 32 + (lane >> 4) * 16));
#pragma unroll
            for (int np = 0; np < 4; ++np) {
                uint32_t w0, w1r, w2, w3;
                ldsm4t(w0, w1r, w2, w3, W1Fs + swz((uint32_t)(lm * 128 + lc * 2 + np * 32)));
#pragma unroll
                for (int mt = 0; mt < 2; ++mt) {
                    mma16816(acc[mt][2 * np],     da[mt][0], da[mt][1], da[mt][2], da[mt][3], w0, w1r);
                    mma16816(acc[mt][2 * np + 1], da[mt][0], da[mt][1], da[mt][2], da[mt][3], w2, w3);
                }
            }
        }

        // ---- GELU -> g A-fragments (fp16), then acc := bias ----
        uint32_t ga[2][4][4];
#pragma unroll
        for (int mt = 0; mt < 2; ++mt)
#pragma unroll
            for (int kg = 0; kg < 4; ++kg) {
                float* e0 = acc[mt][2 * kg];
                float* e1 = acc[mt][2 * kg + 1];
                ga[mt][kg][0] = packh2(gelu_fast(e0[0]), gelu_fast(e0[1]));
                ga[mt][kg][1] = packh2(gelu_fast(e0[2]), gelu_fast(e0[3]));
                ga[mt][kg][2] = packh2(gelu_fast(e1[0]), gelu_fast(e1[1]));
                ga[mt][kg][3] = packh2(gelu_fast(e1[2]), gelu_fast(e1[3]));
            }
#pragma unroll
        for (int nt = 0; nt < 8; ++nt) {
            float2 cv = *(float2*)&cvs[nt * 8 + q2];
#pragma unroll
            for (int mt = 0; mt < 2; ++mt) {
                acc[mt][nt][0] = cv.x; acc[mt][nt][1] = cv.y;
                acc[mt][nt][2] = cv.x; acc[mt][nt][3] = cv.y;
            }
        }

        // ---- prefetch kt=1 raw (latency hidden under phase A) ----
#pragma unroll
        for (int mt = 0; mt < 2; ++mt)
#pragma unroll
            for (int ro = 0; ro < 2; ++ro)
#pragma unroll
                for (int co = 0; co < 2; ++co) {
                    int r = R + mt * 16 + ro * 8 + rg;
                    float2 v = make_float2(0.f, 0.f);
                    if (r < n) v = *(const float2*)&x[(size_t)r * 64 + 16 + q2 + co * 8];
                    raw[1][mt * 4 + ro * 2 + co] = v;
                }

        // ---- phase A: acc += g @ Bf ----
#pragma unroll
        for (int kt = 0; kt < 4; ++kt)
#pragma unroll
            for (int np = 0; np < 4; ++np) {
                uint32_t b0, b1r, b2, b3;
                ldsm4t(b0, b1r, b2, b3,
                       WBFs + swz((uint32_t)((kt * 16 + lm) * 128 + lc * 2 + np * 32)));
#pragma unroll
                for (int mt = 0; mt < 2; ++mt) {
                    mma16816(acc[mt][2 * np],     ga[mt][kt][0], ga[mt][kt][1],
                             ga[mt][kt][2], ga[mt][kt][3], b0, b1r);
                    mma16816(acc[mt][2 * np + 1], ga[mt][kt][0], ga[mt][kt][1],
                             ga[mt][kt][2], ga[mt][kt][3], b2, b3);
                }
            }

        // ---- phase B: acc += xh@Af + xl@Af (fp16 exact split), kt-streamed ----
#pragma unroll
        for (int kt = 0; kt < 4; ++kt) {
            // build fragments for kt from raw[kt&1]
            uint32_t xh[2][4], xl[2][4];
#pragma unroll
            for (int mt = 0; mt < 2; ++mt) {
                float2* rw = &raw[kt & 1][mt * 4];
                splith2(rw[0], xh[mt][0], xl[mt][0]);  // (r, c)
                splith2(rw[2], xh[mt][1], xl[mt][1]);  // (r+8, c)
                splith2(rw[1], xh[mt][2], xl[mt][2]);  // (r, c+8)
                splith2(rw[3], xh[mt][3], xl[mt][3]);  // (r+8, c+8)
            }
            // prefetch kt+2 into the buffer slot just freed
            if (kt < 2) {
#pragma unroll
                for (int mt = 0; mt < 2; ++mt)
#pragma unroll
                    for (int ro = 0; ro < 2; ++ro)
#pragma unroll
                        for (int co = 0; co < 2; ++co) {
                            int r = R + mt * 16 + ro * 8 + rg;
                            float2 v = make_float2(0.f, 0.f);
                            if (r < n)
                                v = *(const float2*)&x[(size_t)r * 64 + (kt + 2) * 16 + q2 + co * 8];
                            raw[kt & 1][mt * 4 + ro * 2 + co] = v;
                        }
            }
#pragma unroll
            for (int np = 0; np < 4; ++np) {
                uint32_t brow = swz((uint32_t)((kt * 16 + lm) * 128 + lc * 2 + np * 32));
                uint32_t a0, a1r, a2, a3;
                ldsm4t(a0, a1r, a2, a3, WAFs + brow);
#pragma unroll
                for (int mt = 0; mt < 2; ++mt) {
                    mma16816(acc[mt][2 * np],     xh[mt][0], xh[mt][1], xh[mt][2], xh[mt][3], a0, a1r);
                    mma16816(acc[mt][2 * np + 1], xh[mt][0], xh[mt][1], xh[mt][2], xh[mt][3], a2, a3);
                    mma16816(acc[mt][2 * np],     xl[mt][0], xl[mt][1], xl[mt][2], xl[mt][3], a0, a1r);
                    mma16816(acc[mt][2 * np + 1], xl[mt][0], xl[mt][1], xl[mt][2], xl[mt][3], a2, a3);
                }
            }
        }

        // ---- LayerNorm + direct STG in fragment layout ----
#pragma unroll
        for (int mt = 0; mt < 2; ++mt) {
            float s0 = 0.f, s1 = 0.f, ss0 = 0.f, ss1 = 0.f;
#pragma unroll
            for (int nt = 0; nt < 8; ++nt) {
                float* a = acc[mt][nt];
                s0 += a[0] + a[1];
                ss0 += a[0] * a[0] + a[1] * a[1];
                s1 += a[2] + a[3];
                ss1 += a[2] * a[2] + a[3] * a[3];
            }
            s0 += __shfl_xor_sync(0xffffffffu, s0, 1);
            s0 += __shfl_xor_sync(0xffffffffu, s0, 2);
            ss0 += __shfl_xor_sync(0xffffffffu, ss0, 1);
            ss0 += __shfl_xor_sync(0xffffffffu, ss0, 2);
            s1 += __shfl_xor_sync(0xffffffffu, s1, 1);
            s1 += __shfl_xor_sync(0xffffffffu, s1, 2);
            ss1 += __shfl_xor_sync(0xffffffffu, ss1, 1);
            ss1 += __shfl_xor_sync(0xffffffffu, ss1, 2);
            float mu0 = s0 * 0.015625f, mu1 = s1 * 0.015625f;
            float r0v = rsqrtf(ss0 * 0.015625f - mu0 * mu0 + 1e-5f);
            float r1v = rsqrtf(ss1 * 0.015625f - mu1 * mu1 + 1e-5f);
            int r0 = R + mt * 16 + rg;
            int r1 = r0 + 8;
#pragma unroll
            for (int nt = 0; nt < 8; ++nt) {
                int nn = nt * 8 + q2;
                float2 gg = *(float2*)&lng[nn];
                float2 bbv = *(float2*)&lnb[nn];
                float* a = acc[mt][nt];
                if (r0 < n)
                    *(float2*)&out[(size_t)r0 * 64 + nn] =
                        make_float2((a[0] - mu0) * r0v * gg.x + bbv.x,
                                    (a[1] - mu0) * r0v * gg.y + bbv.y);
                if (r1 < n)
                    *(float2*)&out[(size_t)r1 * 64 + nn] =
                        make_float2((a[2] - mu1) * r1v * gg.x + bbv.x,
                                    (a[3] - mu1) * r1v * gg.y + bbv.y);
            }
        }
        __syncwarp();  // DLT reuse next tile
    }
}

// ---------------- launch ----------------
extern "C" void kernel_launch(void* const* d_in, const int* in_sizes, int n_in,
                              void* d_out, int out_size) {
    const float* x     = (const float*)d_in[0];
    const float* coord = (const float*)d_in[1];
    const int*   ids   = (const int*)d_in[2];
    const float* W1    = (const float*)d_in[3];
    const float* b1    = (const float*)d_in[4];
    const float* W2    = (const float*)d_in[5];
    const float* b2    = (const float*)d_in[6];
    const float* dw_w  = (const float*)d_in[7];
    const float* dw_b  = (const float*)d_in[8];
    const float* pw_W  = (const float*)d_in[9];
    const float* pw_b  = (const float*)d_in[10];
    const float* ln_g  = (const float*)d_in[11];
    const float* ln_b  = (const float*)d_in[12];
    float* out = (float*)d_out;

    int n = in_sizes[0] / DIM;
    int nbs = (n + 255) / 256;

    k_noop<<<1, 32>>>();   // shifts launch indices so ncu -s 5 lands on k_main
    k_front<<<nbs + 16, 256>>>(coord, ids, n, nbs, W2, dw_w, dw_b, pw_W, pw_b, b2);
    k_centers<<<16, 256>>>();

    int ntiles = (n + TILE - 1) / TILE;
    cudaFuncSetAttribute(k_main, cudaFuncAttributeMaxDynamicSharedMemorySize, SMEM_BYTES);
    k_main<<<296, NT, SMEM_BYTES>>>(x, coord, ids, W1, b1, ln_g, ln_b, out, n, ntiles);
}